// round 3
// baseline (speedup 1.0000x reference)
#include <cuda_runtime.h>
#include <cuda_bf16.h>
#include <cstdint>

// ---------------- problem constants ----------------
static constexpr int B_     = 4096;
static constexpr int D_     = 128;
static constexpr int R_     = 2 * B_;      // 8192 rows
static constexpr int TILE_  = 128;
static constexpr int RT_    = R_ / TILE_;  // 64 tiles per dim
static constexpr int CSPLIT = 4;           // column splits (CTAs per row tile)
static constexpr int NT_    = RT_ / CSPLIT;// 16 col tiles per CTA

static constexpr float INV_T = 10.0f;                    // 1/temperature
static constexpr float K2F   = 14.4269504088896340736f;  // log2(e)/T

// ---------------- device scratch (no allocs allowed) ----------------
__device__ __align__(16) __nv_bfloat16 g_eN[R_ * D_];    // normalized embeddings, bf16
__device__ float g_partial[CSPLIT * R_];                 // per-split row partial exp sums
__device__ float g_pos[R_];                              // positive-pair similarity per row

// ---------------- helpers ----------------
__device__ __forceinline__ uint32_t smem_u32(const void* p) {
    uint32_t a;
    asm("{ .reg .u64 t; cvta.to.shared.u64 t, %1; cvt.u32.u64 %0, t; }" : "=r"(a) : "l"(p));
    return a;
}

#define CP16(dst, src)  asm volatile("cp.async.ca.shared.global [%0], [%1], 16;" :: "r"(dst), "l"(src))
#define CP_COMMIT()     asm volatile("cp.async.commit_group;" ::: "memory")
#define CP_WAIT0()      asm volatile("cp.async.wait_group 0;" ::: "memory")
#define CP_WAIT1()      asm volatile("cp.async.wait_group 1;" ::: "memory")

__device__ __forceinline__ void ldm_x4(uint32_t& r0, uint32_t& r1, uint32_t& r2, uint32_t& r3,
                                       uint32_t addr) {
    asm volatile("ldmatrix.sync.aligned.m8n8.x4.shared.b16 {%0,%1,%2,%3}, [%4];"
                 : "=r"(r0), "=r"(r1), "=r"(r2), "=r"(r3) : "r"(addr));
}

__device__ __forceinline__ void mma16816(float* d, const uint32_t* a, uint32_t b0, uint32_t b1) {
    asm volatile(
        "mma.sync.aligned.m16n8k16.row.col.f32.bf16.bf16.f32 "
        "{%0,%1,%2,%3}, {%4,%5,%6,%7}, {%8,%9}, {%0,%1,%2,%3};"
        : "+f"(d[0]), "+f"(d[1]), "+f"(d[2]), "+f"(d[3])
        : "r"(a[0]), "r"(a[1]), "r"(a[2]), "r"(a[3]), "r"(b0), "r"(b1));
}

// exp(s / T) = 2^(s * log2(e)/T), FFMA-only (no MUFU)
__device__ __forceinline__ float fexpT(float s) {
    float tt = s * K2F;
    float rr = __fadd_rn(tt, 12582912.0f);                  // round-to-int magic (1.5*2^23)
    float fi = __fsub_rn(tt, __fsub_rn(rr, 12582912.0f));   // frac in [-0.5, 0.5]
    float p  = __fmaf_rn(fi, 1.3333558e-3f, 9.6181291e-3f);
    p = __fmaf_rn(fi, p, 5.5504109e-2f);
    p = __fmaf_rn(fi, p, 2.4022651e-1f);
    p = __fmaf_rn(fi, p, 6.9314718e-1f);
    p = __fmaf_rn(fi, p, 1.0f);
    return __int_as_float(__float_as_int(p) + (__float_as_int(rr) << 23));
}

// Swizzled tile layout: 128 rows x 256B; 16B chunk c of row r lives at
// r*256 + ((c ^ (r&7)) * 16)  -> conflict-free for ldmatrix and for stores.
__device__ __forceinline__ uint32_t tile_off(int row, int chunk) {
    return (uint32_t)(row * 256 + (((chunk ^ (row & 7)) & 15) << 4));
}

// Issue cp.async loads of one 128x128 bf16 tile (32KB) from g_eN row gRow0.
__device__ __forceinline__ void issue_tile_load(uint32_t sdst, int gRow0, int tid) {
    const char* src = (const char*)(g_eN + (size_t)gRow0 * D_);
#pragma unroll
    for (int i = 0; i < 8; ++i) {
        int idx = i * 256 + tid;          // 16B chunk index 0..2047
        int row = idx >> 4;
        int ch  = idx & 15;
        CP16(sdst + tile_off(row, ch), src + (size_t)idx * 16);
    }
}

// ---------------- kernel 1: normalize to bf16 ----------------
__global__ void normalize_kernel(const float* __restrict__ v1, const float* __restrict__ v2) {
    int warp = threadIdx.x >> 5, lid = threadIdx.x & 31;
    int row = blockIdx.x * 8 + warp;
    const float* src = (row < B_) ? (v1 + (size_t)row * D_) : (v2 + (size_t)(row - B_) * D_);
    float4 a = reinterpret_cast<const float4*>(src)[lid];
    float ss = a.x * a.x + a.y * a.y + a.z * a.z + a.w * a.w;
#pragma unroll
    for (int o = 16; o; o >>= 1) ss += __shfl_xor_sync(0xFFFFFFFFu, ss, o);
    float inv = 1.0f / fmaxf(sqrtf(ss), 1e-8f);
    __nv_bfloat162* dst = reinterpret_cast<__nv_bfloat162*>(g_eN + (size_t)row * D_);
    dst[lid * 2]     = __floats2bfloat162_rn(a.x * inv, a.y * inv);
    dst[lid * 2 + 1] = __floats2bfloat162_rn(a.z * inv, a.w * inv);
}

// ---------------- kernel 2: fused bf16 HMMA GEMM + exp row-sum ----------------
__global__ void __launch_bounds__(256, 2) simlse_kernel() {
    extern __shared__ char smem[];
    const int tid  = threadIdx.x;
    const int warp = tid >> 5;
    const int l    = tid & 31;
    const int mw   = warp >> 2;       // 0..1  (M warp, 64 rows each)
    const int nw   = warp & 3;        // 0..3  (N warp, 32 cols each)
    const int rt   = blockIdx.y;      // row tile 0..63
    const int cs   = blockIdx.x;      // column split 0..3
    const int pt   = rt ^ (RT_ / 2);  // partner (positive) tile

    const uint32_t sb = smem_u32(smem);
    const uint32_t sA  = sb;
    const uint32_t sB0 = sb + 32768;
    const uint32_t sB1 = sb + 65536;
    float* sred = reinterpret_cast<float*>(smem + 98304);   // [128][4]

    // Prologue: A tile + B tile 0 (group), B tile 1 (group)
    issue_tile_load(sA,  rt * TILE_, tid);
    issue_tile_load(sB0, (cs * NT_ + 0) * TILE_, tid);
    CP_COMMIT();
    if (NT_ > 1) { issue_tile_load(sB1, (cs * NT_ + 1) * TILE_, tid); CP_COMMIT(); }

    const int lane15 = l & 15;
    const int lhi    = l >> 4;

    float acc[4][4][4];     // [mfrag][nfrag][e]
    float rowacc[8];        // [mfrag][half]
#pragma unroll
    for (int i = 0; i < 8; ++i) rowacc[i] = 0.0f;

    for (int t = 0; t < NT_; ++t) {
        // wait for tile t's cp.async group
        if (t < NT_ - 1) CP_WAIT1(); else CP_WAIT0();
        __syncthreads();

        const uint32_t sB = (t & 1) ? sB1 : sB0;

#pragma unroll
        for (int mf = 0; mf < 4; ++mf)
#pragma unroll
            for (int nf = 0; nf < 4; ++nf)
#pragma unroll
                for (int e = 0; e < 4; ++e) acc[mf][nf][e] = 0.0f;

        // ---- MMA mainloop over K = 128 (8 x k16) ----
#pragma unroll
        for (int ks = 0; ks < 8; ++ks) {
            uint32_t a[4][4];
#pragma unroll
            for (int mf = 0; mf < 4; ++mf) {
                int row = mw * 64 + mf * 16 + lane15;
                ldm_x4(a[mf][0], a[mf][1], a[mf][2], a[mf][3],
                       sA + tile_off(row, 2 * ks + lhi));
            }
            uint32_t b[2][4];
#pragma unroll
            for (int nf2 = 0; nf2 < 2; ++nf2) {
                int row = nw * 32 + nf2 * 16 + lane15;
                ldm_x4(b[nf2][0], b[nf2][1], b[nf2][2], b[nf2][3],
                       sB + tile_off(row, 2 * ks + lhi));
            }
#pragma unroll
            for (int mf = 0; mf < 4; ++mf)
#pragma unroll
                for (int nf2 = 0; nf2 < 2; ++nf2) {
                    mma16816(acc[mf][nf2 * 2 + 0], a[mf], b[nf2][0], b[nf2][2]);
                    mma16816(acc[mf][nf2 * 2 + 1], a[mf], b[nf2][1], b[nf2][3]);
                }
        }

        __syncthreads();   // all warps done reading buffer t
        if (t + 2 < NT_) {
            issue_tile_load((t & 1) ? sB1 : sB0, (cs * NT_ + t + 2) * TILE_, tid);
            CP_COMMIT();
        }

        // ---- epilogue: exp + row-sum (overlaps next tile's cp.async) ----
        const int ct    = cs * NT_ + t;
        const bool diagT = (ct == rt);
        const bool posT  = (ct == pt);

        if (!diagT && !posT) {
#pragma unroll
            for (int mf = 0; mf < 4; ++mf)
#pragma unroll
                for (int nf = 0; nf < 4; ++nf)
#pragma unroll
                    for (int e = 0; e < 4; ++e)
                        rowacc[mf * 2 + (e >> 1)] += fexpT(acc[mf][nf][e]);
        } else {
#pragma unroll
            for (int mf = 0; mf < 4; ++mf)
#pragma unroll
                for (int nf = 0; nf < 4; ++nf)
#pragma unroll
                    for (int e = 0; e < 4; ++e) {
                        float s = acc[mf][nf][e];
                        int row = mw * 64 + mf * 16 + (l >> 2) + ((e >> 1) << 3);
                        int col = nw * 32 + nf * 8 + ((l & 3) << 1) + (e & 1);
                        float ev = fexpT(s);
                        if (row == col) {
                            if (diagT) ev = 0.0f;                         // mask self-sim
                            if (posT)  g_pos[rt * TILE_ + row] = s;       // positive pair
                        }
                        rowacc[mf * 2 + (e >> 1)] += ev;
                    }
        }
    }

    // ---- reduce row sums: 4 lanes (same rows) then 4 N-warps ----
#pragma unroll
    for (int i = 0; i < 8; ++i) {
        float v = rowacc[i];
        v += __shfl_xor_sync(0xFFFFFFFFu, v, 1);
        v += __shfl_xor_sync(0xFFFFFFFFu, v, 2);
        rowacc[i] = v;
    }
    __syncthreads();
    if ((l & 3) == 0) {
#pragma unroll
        for (int mf = 0; mf < 4; ++mf)
#pragma unroll
            for (int h = 0; h < 2; ++h) {
                int row = mw * 64 + mf * 16 + (l >> 2) + h * 8;
                sred[row * 4 + nw] = rowacc[mf * 2 + h];
            }
    }
    __syncthreads();
    if (tid < TILE_) {
        float s = sred[tid * 4] + sred[tid * 4 + 1] + sred[tid * 4 + 2] + sred[tid * 4 + 3];
        g_partial[cs * R_ + rt * TILE_ + tid] = s;
    }
}

// ---------------- kernel 3: finalize loss ----------------
__global__ void finalize_kernel(float* __restrict__ out) {
    __shared__ double sred[256];
    int tid = threadIdx.x;
    double local = 0.0;
    for (int r = tid; r < R_; r += 256) {
        float S = g_partial[r] + g_partial[R_ + r] + g_partial[2 * R_ + r] + g_partial[3 * R_ + r];
        float pl = g_pos[r] * INV_T;
        float Sf = S + expf(pl);             // + explicit positive column
        local += (double)(logf(Sf) - pl);    // LSE - pos/T
    }
    sred[tid] = local;
    __syncthreads();
#pragma unroll
    for (int s = 128; s > 0; s >>= 1) {
        if (tid < s) sred[tid] += sred[tid + s];
        __syncthreads();
    }
    if (tid == 0) out[0] = (float)(sred[0] / (double)R_);
}

// ---------------- launch ----------------
extern "C" void kernel_launch(void* const* d_in, const int* in_sizes, int n_in,
                              void* d_out, int out_size) {
    (void)in_sizes; (void)n_in; (void)out_size;
    const float* v1 = (const float*)d_in[0];
    const float* v2 = (const float*)d_in[1];
    float* out = (float*)d_out;

    normalize_kernel<<<R_ / 8, 256>>>(v1, v2);

    const int smem_bytes = 3 * 32768 + 2048;   // A + B0 + B1 + reduction
    cudaFuncSetAttribute(simlse_kernel, cudaFuncAttributeMaxDynamicSharedMemorySize, smem_bytes);
    dim3 grid(CSPLIT, RT_);
    simlse_kernel<<<grid, 256, smem_bytes>>>();

    finalize_kernel<<<1, 256>>>(out);
}

// round 4
// speedup vs baseline: 1.7142x; 1.7142x over previous
#include <cuda_runtime.h>
#include <cuda_bf16.h>
#include <cstdint>

// ---------------- problem constants ----------------
static constexpr int B_     = 4096;
static constexpr int D_     = 128;
static constexpr int R_     = 2 * B_;      // 8192 rows
static constexpr int TILE_  = 128;
static constexpr int RT_    = R_ / TILE_;  // 64 tiles per dim
static constexpr int STRIPW = 8;           // column tiles per strip
static constexpr int STRIPS = 288;         // sum_rt ceil((64-rt)/8)
static constexpr int SLOTS  = 72;          // 64 colsum slots + 8 rowstrip slots

static constexpr float INV_T = 10.0f;                    // 1/temperature
static constexpr float K2F   = 14.4269504088896340736f;  // log2(e)/T

// ---------------- device scratch (no allocs allowed) ----------------
__device__ __align__(16) __nv_bfloat16 g_eN[R_ * D_];    // normalized embeddings, bf16
__device__ float  g_partial[SLOTS * R_];                 // partial exp row sums
__device__ float  g_pos[R_];                             // positive-pair similarity per row
__device__ double g_bsum[64];                            // per-block loss sums

// ---------------- helpers ----------------
__device__ __forceinline__ uint32_t smem_u32(const void* p) {
    uint32_t a;
    asm("{ .reg .u64 t; cvta.to.shared.u64 t, %1; cvt.u32.u64 %0, t; }" : "=r"(a) : "l"(p));
    return a;
}

#define CP16(dst, src)  asm volatile("cp.async.ca.shared.global [%0], [%1], 16;" :: "r"(dst), "l"(src))
#define CP_COMMIT()     asm volatile("cp.async.commit_group;" ::: "memory")
#define CP_WAIT0()      asm volatile("cp.async.wait_group 0;" ::: "memory")
#define CP_WAIT1()      asm volatile("cp.async.wait_group 1;" ::: "memory")

__device__ __forceinline__ void ldm_x4(uint32_t& r0, uint32_t& r1, uint32_t& r2, uint32_t& r3,
                                       uint32_t addr) {
    asm volatile("ldmatrix.sync.aligned.m8n8.x4.shared.b16 {%0,%1,%2,%3}, [%4];"
                 : "=r"(r0), "=r"(r1), "=r"(r2), "=r"(r3) : "r"(addr));
}

__device__ __forceinline__ void mma16816(float* d, const uint32_t* a, uint32_t b0, uint32_t b1) {
    asm volatile(
        "mma.sync.aligned.m16n8k16.row.col.f32.bf16.bf16.f32 "
        "{%0,%1,%2,%3}, {%4,%5,%6,%7}, {%8,%9}, {%0,%1,%2,%3};"
        : "+f"(d[0]), "+f"(d[1]), "+f"(d[2]), "+f"(d[3])
        : "r"(a[0]), "r"(a[1]), "r"(a[2]), "r"(a[3]), "r"(b0), "r"(b1));
}

// exp(s / T) = 2^(s * log2(e)/T), FFMA-only (no MUFU)
__device__ __forceinline__ float fexpT(float s) {
    float tt = s * K2F;
    float rr = __fadd_rn(tt, 12582912.0f);                  // round-to-int magic (1.5*2^23)
    float fi = __fsub_rn(tt, __fsub_rn(rr, 12582912.0f));   // frac in [-0.5, 0.5]
    float p  = __fmaf_rn(fi, 1.3333558e-3f, 9.6181291e-3f);
    p = __fmaf_rn(fi, p, 5.5504109e-2f);
    p = __fmaf_rn(fi, p, 2.4022651e-1f);
    p = __fmaf_rn(fi, p, 6.9314718e-1f);
    p = __fmaf_rn(fi, p, 1.0f);
    return __int_as_float(__float_as_int(p) + (__float_as_int(rr) << 23));
}

// Swizzled tile layout: 128 rows x 256B; 16B chunk c of row r lives at
// r*256 + ((c ^ (r&7)) * 16)  -> conflict-free for ldmatrix and for stores.
__device__ __forceinline__ uint32_t tile_off(int row, int chunk) {
    return (uint32_t)(row * 256 + (((chunk ^ (row & 7)) & 15) << 4));
}

// Issue cp.async loads of one 128x128 bf16 tile (32KB) from g_eN row gRow0.
__device__ __forceinline__ void issue_tile_load(uint32_t sdst, int gRow0, int tid) {
    const char* src = (const char*)(g_eN + (size_t)gRow0 * D_);
#pragma unroll
    for (int i = 0; i < 8; ++i) {
        int idx = i * 256 + tid;          // 16B chunk index 0..2047
        int row = idx >> 4;
        int ch  = idx & 15;
        CP16(sdst + tile_off(row, ch), src + (size_t)idx * 16);
    }
}

// ---------------- kernel 1: normalize to bf16 ----------------
__global__ void normalize_kernel(const float* __restrict__ v1, const float* __restrict__ v2) {
    int warp = threadIdx.x >> 5, lid = threadIdx.x & 31;
    int row = blockIdx.x * 8 + warp;
    const float* src = (row < B_) ? (v1 + (size_t)row * D_) : (v2 + (size_t)(row - B_) * D_);
    float4 a = reinterpret_cast<const float4*>(src)[lid];
    float ss = a.x * a.x + a.y * a.y + a.z * a.z + a.w * a.w;
#pragma unroll
    for (int o = 16; o; o >>= 1) ss += __shfl_xor_sync(0xFFFFFFFFu, ss, o);
    float inv = 1.0f / fmaxf(sqrtf(ss), 1e-8f);
    __nv_bfloat162* dst = reinterpret_cast<__nv_bfloat162*>(g_eN + (size_t)row * D_);
    dst[lid * 2]     = __floats2bfloat162_rn(a.x * inv, a.y * inv);
    dst[lid * 2 + 1] = __floats2bfloat162_rn(a.z * inv, a.w * inv);
}

// ---------------- kernel 2: triangular fused GEMM + exp row/col sums ----------------
__global__ void __launch_bounds__(256, 2) simlse_kernel() {
    extern __shared__ char smem[];
    const int tid  = threadIdx.x;
    const int warp = tid >> 5;
    const int l    = tid & 31;
    const int mw   = warp >> 2;       // 0..1  (M warp, 64 rows each)
    const int nw   = warp & 3;        // 0..3  (N warp, 32 cols each)

    // ---- decode strip: bid -> (row tile rt, strip index k) ----
    int rt = 0, k = 0;
    {
        int b = blockIdx.x;
        for (rt = 0; rt < RT_; ++rt) {
            int n = (RT_ - rt + STRIPW - 1) >> 3;
            if (b < n) { k = b; break; }
            b -= n;
        }
    }
    const int c0  = rt + k * STRIPW;
    const int len = min(STRIPW, RT_ - c0);

    const uint32_t sb  = smem_u32(smem);
    const uint32_t sA  = sb;
    const uint32_t sB0 = sb + 32768;
    const uint32_t sB1 = sb + 65536;
    float* sred = reinterpret_cast<float*>(smem + 98304);          // [128][4]
    float* scol = reinterpret_cast<float*>(smem + 98304 + 2048);   // [2][4][4][8]

    // Prologue: A tile + B tile 0 (group), B tile 1 (group)
    issue_tile_load(sA,  rt * TILE_, tid);
    issue_tile_load(sB0, c0 * TILE_, tid);
    CP_COMMIT();
    if (len > 1) { issue_tile_load(sB1, (c0 + 1) * TILE_, tid); CP_COMMIT(); }

    const int lane15 = l & 15;
    const int lhi    = l >> 4;

    float acc[4][4][4];     // [mfrag][nfrag][e]
    float rowacc[8];        // [mfrag][half]
#pragma unroll
    for (int i = 0; i < 8; ++i) rowacc[i] = 0.0f;

    for (int t = 0; t < len; ++t) {
        const int ct = c0 + t;
        if (t < len - 1) CP_WAIT1(); else CP_WAIT0();
        __syncthreads();

        const uint32_t sB = (t & 1) ? sB1 : sB0;

#pragma unroll
        for (int mf = 0; mf < 4; ++mf)
#pragma unroll
            for (int nf = 0; nf < 4; ++nf)
#pragma unroll
                for (int e = 0; e < 4; ++e) acc[mf][nf][e] = 0.0f;

        // ---- MMA mainloop over K = 128 (8 x k16) ----
#pragma unroll
        for (int ks = 0; ks < 8; ++ks) {
            uint32_t a[4][4];
#pragma unroll
            for (int mf = 0; mf < 4; ++mf) {
                int row = mw * 64 + mf * 16 + lane15;
                ldm_x4(a[mf][0], a[mf][1], a[mf][2], a[mf][3],
                       sA + tile_off(row, 2 * ks + lhi));
            }
            uint32_t b[2][4];
#pragma unroll
            for (int nf2 = 0; nf2 < 2; ++nf2) {
                int row = nw * 32 + nf2 * 16 + lane15;
                ldm_x4(b[nf2][0], b[nf2][1], b[nf2][2], b[nf2][3],
                       sB + tile_off(row, 2 * ks + lhi));
            }
#pragma unroll
            for (int mf = 0; mf < 4; ++mf)
#pragma unroll
                for (int nf2 = 0; nf2 < 2; ++nf2) {
                    mma16816(acc[mf][nf2 * 2 + 0], a[mf], b[nf2][0], b[nf2][2]);
                    mma16816(acc[mf][nf2 * 2 + 1], a[mf], b[nf2][1], b[nf2][3]);
                }
        }

        __syncthreads();   // all warps done reading buffer t
        if (t + 2 < len) {
            issue_tile_load((t & 1) ? sB1 : sB0, (c0 + t + 2) * TILE_, tid);
            CP_COMMIT();
        }

        // ---- epilogue: exp, row sums, column sums ----
        const bool diagT = (ct == rt);
        const bool posT  = (ct == rt + RT_ / 2);

        float cacc[8];
#pragma unroll
        for (int i = 0; i < 8; ++i) cacc[i] = 0.0f;

        if (diagT) {
            // self-sim masked; tile holds both (i,j) and (j,i) -> row sums only
#pragma unroll
            for (int mf = 0; mf < 4; ++mf)
#pragma unroll
                for (int nf = 0; nf < 4; ++nf)
#pragma unroll
                    for (int e = 0; e < 4; ++e) {
                        int row = mw * 64 + mf * 16 + (l >> 2) + ((e >> 1) << 3);
                        int col = nw * 32 + nf * 8 + ((l & 3) << 1) + (e & 1);
                        float ev = (row == col) ? 0.0f : fexpT(acc[mf][nf][e]);
                        rowacc[mf * 2 + (e >> 1)] += ev;
                    }
        } else if (posT) {
#pragma unroll
            for (int mf = 0; mf < 4; ++mf)
#pragma unroll
                for (int nf = 0; nf < 4; ++nf)
#pragma unroll
                    for (int e = 0; e < 4; ++e) {
                        float s = acc[mf][nf][e];
                        int row = mw * 64 + mf * 16 + (l >> 2) + ((e >> 1) << 3);
                        int col = nw * 32 + nf * 8 + ((l & 3) << 1) + (e & 1);
                        if (row == col) {                       // positive pair (both views)
                            g_pos[rt * TILE_ + row] = s;
                            g_pos[ct * TILE_ + row] = s;
                        }
                        float ev = fexpT(s);
                        rowacc[mf * 2 + (e >> 1)] += ev;
                        cacc[nf * 2 + (e & 1)]    += ev;
                    }
        } else {
            // fast path: no index math beyond accumulator selection
#pragma unroll
            for (int mf = 0; mf < 4; ++mf)
#pragma unroll
                for (int nf = 0; nf < 4; ++nf)
#pragma unroll
                    for (int e = 0; e < 4; ++e) {
                        float ev = fexpT(acc[mf][nf][e]);
                        rowacc[mf * 2 + (e >> 1)] += ev;
                        cacc[nf * 2 + (e & 1)]    += ev;
                    }
        }

        if (!diagT) {
            // reduce column sums over rows: lanes l>>2 (xor 4,8,16), then 2 M-warps via smem
#pragma unroll
            for (int i = 0; i < 8; ++i) {
                float v = cacc[i];
                v += __shfl_xor_sync(0xFFFFFFFFu, v, 4);
                v += __shfl_xor_sync(0xFFFFFFFFu, v, 8);
                v += __shfl_xor_sync(0xFFFFFFFFu, v, 16);
                cacc[i] = v;
            }
            if (l < 4) {
#pragma unroll
                for (int i = 0; i < 8; ++i)
                    scol[((mw * 4 + nw) * 4 + l) * 8 + i] = cacc[i];
            }
            __syncthreads();
            if (tid < TILE_) {
                int o = tid & 31, nw2 = tid >> 5;
                int nf = o >> 3, l3 = (o >> 1) & 3, idx = nf * 2 + (o & 1);
                float v = scol[((0 * 4 + nw2) * 4 + l3) * 8 + idx]
                        + scol[((1 * 4 + nw2) * 4 + l3) * 8 + idx];
                g_partial[(size_t)rt * R_ + ct * TILE_ + tid] = v;   // colsum slot = rt
            }
            __syncthreads();
        }
    }

    // ---- strip row sums -> slot 64+k ----
#pragma unroll
    for (int i = 0; i < 8; ++i) {
        float v = rowacc[i];
        v += __shfl_xor_sync(0xFFFFFFFFu, v, 1);
        v += __shfl_xor_sync(0xFFFFFFFFu, v, 2);
        rowacc[i] = v;
    }
    __syncthreads();
    if ((l & 3) == 0) {
#pragma unroll
        for (int mf = 0; mf < 4; ++mf)
#pragma unroll
            for (int h = 0; h < 2; ++h) {
                int row = mw * 64 + mf * 16 + (l >> 2) + h * 8;
                sred[row * 4 + nw] = rowacc[mf * 2 + h];
            }
    }
    __syncthreads();
    if (tid < TILE_) {
        float s = sred[tid * 4] + sred[tid * 4 + 1] + sred[tid * 4 + 2] + sred[tid * 4 + 3];
        g_partial[(size_t)(64 + k) * R_ + rt * TILE_ + tid] = s;
    }
}

// ---------------- kernel 3a: per-row loss, per-block sum ----------------
__global__ void rowloss_kernel() {
    __shared__ double sd[128];
    const int b   = blockIdx.x;        // row block 0..63
    const int tid = threadIdx.x;       // row within block
    const int r   = b * TILE_ + tid;

    float S = 0.0f;
    for (int s = 0; s < b; ++s)                    // colsum slots from tiles (s, b), s<b
        S += g_partial[(size_t)s * R_ + r];
    const int ns = (RT_ - b + STRIPW - 1) >> 3;    // row-strip slots of row b
    for (int j = 0; j < ns; ++j)
        S += g_partial[(size_t)(64 + j) * R_ + r];

    float pl = g_pos[r] * INV_T;
    float loss = logf(S + expf(pl)) - pl;          // LSE - pos/T (positive column explicit)

    sd[tid] = (double)loss;
    __syncthreads();
#pragma unroll
    for (int s = 64; s > 0; s >>= 1) {
        if (tid < s) sd[tid] += sd[tid + s];
        __syncthreads();
    }
    if (tid == 0) g_bsum[b] = sd[0];
}

// ---------------- kernel 3b: final mean ----------------
__global__ void final_kernel(float* __restrict__ out) {
    __shared__ double sd[64];
    int tid = threadIdx.x;
    sd[tid] = g_bsum[tid];
    __syncthreads();
#pragma unroll
    for (int s = 32; s > 0; s >>= 1) {
        if (tid < s) sd[tid] += sd[tid + s];
        __syncthreads();
    }
    if (tid == 0) out[0] = (float)(sd[0] / (double)R_);
}

// ---------------- launch ----------------
extern "C" void kernel_launch(void* const* d_in, const int* in_sizes, int n_in,
                              void* d_out, int out_size) {
    (void)in_sizes; (void)n_in; (void)out_size;
    const float* v1 = (const float*)d_in[0];
    const float* v2 = (const float*)d_in[1];
    float* out = (float*)d_out;

    normalize_kernel<<<R_ / 8, 256>>>(v1, v2);

    const int smem_bytes = 3 * 32768 + 2048 + 1024;   // A + B0 + B1 + sred + scol
    cudaFuncSetAttribute(simlse_kernel, cudaFuncAttributeMaxDynamicSharedMemorySize, smem_bytes);
    simlse_kernel<<<STRIPS, 256, smem_bytes>>>();

    rowloss_kernel<<<RT_, TILE_>>>();
    final_kernel<<<1, 64>>>(out);
}